// round 3
// baseline (speedup 1.0000x reference)
#include <cuda_runtime.h>
#include <math.h>

#define BB 32
#define CC 256
#define CR 64
#define HW 16384   // 128*128

// allocation-free scratch: pooled means only (MLP intermediates live in smem)
__device__ float g_f0[BB * CC];

// ---------------------------------------------------------------------------
// Kernel 1: f0[b,c] = mean over H*W of x[b,c,:,:]
// one block per (b,c) row: 4096 float4; 256 threads x 16 float4 (DRAM-bound)
// __ldcs: read-once streaming data, evict-first in L2.
// ---------------------------------------------------------------------------
__global__ __launch_bounds__(256) void row_mean_kernel(const float* __restrict__ x) {
    const int row = blockIdx.x;                  // b*C + c
    const float4* __restrict__ p =
        reinterpret_cast<const float4*>(x) + (size_t)row * (HW / 4);
    const int t = threadIdx.x;

    float s = 0.0f;
#pragma unroll
    for (int k = 0; k < 16; k++) {
        float4 v = __ldcs(p + k * 256 + t);
        s += (v.x + v.y) + (v.z + v.w);
    }

#pragma unroll
    for (int o = 16; o > 0; o >>= 1)
        s += __shfl_xor_sync(0xffffffffu, s, o);

    __shared__ float part[8];
    if ((t & 31) == 0) part[t >> 5] = s;
    __syncthreads();

    if (t < 8) {
        float v = part[t];
#pragma unroll
        for (int o = 4; o > 0; o >>= 1)
            v += __shfl_xor_sync(0x000000ffu, v, o);
        if (t == 0) g_f0[row] = v * (1.0f / HW);
    }
}

// ---------------------------------------------------------------------------
// Kernel 2: fully fused SE-MLP. grid = 32 blocks (one per batch b), 256 thr.
//   stage1: h[j]  = relu(f0[b,:] . W1[j,:])        j=0..63   (warp-dots)
//   stage2: p[c]  = sigmoid(h . W2[c,:]) * f0[b,c] c=0..255  (warp-dots)
//   stage3: out[b,o] = p . W3[o,:] + b3[o]         o=0..1    (warp-dots)
// All weight LDGs are lane-consecutive (coalesced); intermediates in smem.
// ---------------------------------------------------------------------------
__global__ __launch_bounds__(256) void fused_mlp_kernel(const float* __restrict__ W1,
                                                        const float* __restrict__ W2,
                                                        const float* __restrict__ W3,
                                                        const float* __restrict__ b3,
                                                        float* __restrict__ out) {
    __shared__ float f0s[CC];
    __shared__ float hs[CR];
    __shared__ float ps[CC];

    const int b    = blockIdx.x;
    const int t    = threadIdx.x;
    const int warp = t >> 5;
    const int lane = t & 31;

    // load f0[b,:] into smem (coalesced)
    if (t < CC) f0s[t] = g_f0[b * CC + t];
    __syncthreads();

    // ---- stage 1: 64 warp-dots of length 256, 8 per warp, fully unrolled ---
    {
#pragma unroll
        for (int pass = 0; pass < 8; pass++) {
            const int j = pass * 8 + warp;
            const float* __restrict__ w = W1 + j * CC;
            float acc = 0.0f;
#pragma unroll
            for (int k = 0; k < 8; k++) {
                const int c = k * 32 + lane;
                acc = fmaf(f0s[c], w[c], acc);
            }
#pragma unroll
            for (int o = 16; o > 0; o >>= 1)
                acc += __shfl_xor_sync(0xffffffffu, acc, o);
            if (lane == 0) hs[j] = fmaxf(acc, 0.0f);
        }
    }
    __syncthreads();

    // ---- stage 2: 256 warp-dots of length 64, 32 per warp, 4-wide ILP ------
    {
        const float hv0 = hs[lane];        // loop-invariant h values
        const float hv1 = hs[lane + 32];
#pragma unroll
        for (int cc = 0; cc < 32; cc += 4) {
            float a0 = 0.f, a1 = 0.f, a2 = 0.f, a3 = 0.f;
#pragma unroll
            for (int u = 0; u < 4; u++) {
                const int c = warp * 32 + cc + u;
                const float* __restrict__ w = W2 + c * CR;
                const float s = fmaf(hv0, w[lane], hv1 * w[lane + 32]);
                if (u == 0) a0 = s; else if (u == 1) a1 = s;
                else if (u == 2) a2 = s; else a3 = s;
            }
#pragma unroll
            for (int o = 16; o > 0; o >>= 1) {
                a0 += __shfl_xor_sync(0xffffffffu, a0, o);
                a1 += __shfl_xor_sync(0xffffffffu, a1, o);
                a2 += __shfl_xor_sync(0xffffffffu, a2, o);
                a3 += __shfl_xor_sync(0xffffffffu, a3, o);
            }
            if (lane < 4) {
                const int c = warp * 32 + cc + lane;
                const float acc = (lane == 0) ? a0 : (lane == 1) ? a1
                                 : (lane == 2) ? a2 : a3;
                // a_i is the full sum in every lane after butterfly reduce
                const float gsig = 1.0f / (1.0f + __expf(-acc));
                ps[c] = gsig * f0s[c];
            }
        }
    }
    __syncthreads();

    // ---- stage 3: 2 warp-dots of length 256 ------------------------------
    if (warp < 2) {
        const int o = warp;
        const float* __restrict__ w = W3 + o * CC;
        float acc = 0.0f;
#pragma unroll
        for (int k = 0; k < 8; k++) {
            const int c = k * 32 + lane;
            acc = fmaf(ps[c], w[c], acc);
        }
#pragma unroll
        for (int s = 16; s > 0; s >>= 1)
            acc += __shfl_xor_sync(0xffffffffu, acc, s);
        if (lane == 0) out[b * 2 + o] = acc + b3[o];
    }
}

// ---------------------------------------------------------------------------
extern "C" void kernel_launch(void* const* d_in, const int* in_sizes, int n_in,
                              void* d_out, int out_size) {
    const float* x  = (const float*)d_in[0];  // (32,256,128,128)
    const float* W1 = (const float*)d_in[1];  // (64,256)
    const float* W2 = (const float*)d_in[2];  // (256,64)
    const float* W3 = (const float*)d_in[3];  // (2,256)
    const float* b3 = (const float*)d_in[4];  // (2,)
    float* out = (float*)d_out;               // (32,2)

    row_mean_kernel<<<BB * CC, 256>>>(x);
    fused_mlp_kernel<<<BB, 256>>>(W1, W2, W3, b3, out);
}